// round 11
// baseline (speedup 1.0000x reference)
#include <cuda_runtime.h>
#include <cuda_fp16.h>
#include <cstdint>

#define MM 16
#define KK 8192
#define NN 8192
#define KCH 8             // split-K chunks
#define KC 1024           // k per chunk (8 groups of 128)
#define RW 520            // smem x row stride in WORDS (== 8 mod 32 -> LDS.64 conflict-free)

// fp32 partials: [KCH][M][N]
__device__ float g_partial[KCH * MM * NN];

__device__ __forceinline__ void mma16816(float c[4],
                                         unsigned a0, unsigned a1, unsigned a2, unsigned a3,
                                         unsigned b0, unsigned b1) {
    asm volatile(
        "mma.sync.aligned.m16n8k16.row.col.f32.f16.f16.f32 "
        "{%0,%1,%2,%3}, {%4,%5,%6,%7}, {%8,%9}, {%0,%1,%2,%3};\n"
        : "+f"(c[0]), "+f"(c[1]), "+f"(c[2]), "+f"(c[3])
        : "r"(a0), "r"(a1), "r"(a2), "r"(a3), "r"(b0), "r"(b1));
}

// Nibbles t,t+4 of w -> exact fp16x2 (q-8, q'-8), then *s in fp16 (one rounding,
// bit-identical to the reference's fp16 (q-8)*scale).
__device__ __forceinline__ unsigned dqs(unsigned w, unsigned sh4, __half2 s2) {
    unsigned v = ((w >> sh4) & 0x000F000Fu) | 0x64006400u;   // (1024+q, 1024+q')
    __half2 hv = *reinterpret_cast<__half2*>(&v);
    __half2 r = __hmul2(__hsub2(hv, __float2half2_rn(1032.0f)), s2);
    return *reinterpret_cast<unsigned*>(&r);
}

__global__ __launch_bounds__(128, 4)
void q4_gemm_mma(const float* __restrict__ x,
                 const int* __restrict__ qw,
                 const float* __restrict__ scales) {
    __shared__ __align__(16) __half xs[MM * RW * 2];   // 16 rows * 520 words = 33280 B

    const int tid = threadIdx.x;
    const int kc = blockIdx.y;
    const int warp = tid >> 5;
    const int lane = tid & 31;
    const int g = lane >> 2;        // 0..7
    const int t = lane & 3;         // 0..3
    const unsigned sh4 = 4u * t;
    const int nbase = blockIdx.x * 128 + warp * 32;    // warp owns n32 (4 tiles)

    // ---- Stage x chunk [16][1024] -> word-interleaved fp16 layout ----
    // Per k16 step kt: 8 words [b0w0,b1w0,b0w1,b1w1,b0w2,b1w2,b0w3,b1w3],
    // b0 = k 16kt..+7, b1 = +8..+15, bXwc = halves (k_c, k_{c+4}).
    for (int it = 0; it < 8; ++it) {
        int idx = it * 128 + tid;          // 1024 tasks: (m, kt)
        int m = idx >> 6;
        int kt = idx & 63;
        const float* xp = x + (size_t)m * KK + kc * KC + kt * 16;
        float4 lo0 = *reinterpret_cast<const float4*>(xp);
        float4 lo1 = *reinterpret_cast<const float4*>(xp + 4);
        float4 hi0 = *reinterpret_cast<const float4*>(xp + 8);
        float4 hi1 = *reinterpret_cast<const float4*>(xp + 12);
        __half2 w0 = __floats2half2_rn(lo0.x, lo1.x);   // (k0,k4)
        __half2 w1 = __floats2half2_rn(hi0.x, hi1.x);   // (k8,k12)
        __half2 w2 = __floats2half2_rn(lo0.y, lo1.y);   // (k1,k5)
        __half2 w3 = __floats2half2_rn(hi0.y, hi1.y);   // (k9,k13)
        __half2 w4 = __floats2half2_rn(lo0.z, lo1.z);   // (k2,k6)
        __half2 w5 = __floats2half2_rn(hi0.z, hi1.z);   // (k10,k14)
        __half2 w6 = __floats2half2_rn(lo0.w, lo1.w);   // (k3,k7)
        __half2 w7 = __floats2half2_rn(hi0.w, hi1.w);   // (k11,k15)
        uint4 p0, p1;
        p0.x = *reinterpret_cast<unsigned*>(&w0);
        p0.y = *reinterpret_cast<unsigned*>(&w1);
        p0.z = *reinterpret_cast<unsigned*>(&w2);
        p0.w = *reinterpret_cast<unsigned*>(&w3);
        p1.x = *reinterpret_cast<unsigned*>(&w4);
        p1.y = *reinterpret_cast<unsigned*>(&w5);
        p1.z = *reinterpret_cast<unsigned*>(&w6);
        p1.w = *reinterpret_cast<unsigned*>(&w7);
        __half* dst = &xs[(size_t)m * RW * 2 + kt * 16];
        *reinterpret_cast<uint4*>(dst)     = p0;
        *reinterpret_cast<uint4*>(dst + 8) = p1;
    }
    __syncthreads();

    // ---- Main loop: 4 interleaved n8-tiles, software-pipelined weight loads ----
    float cm[4][4];
#pragma unroll
    for (int j = 0; j < 4; ++j)
#pragma unroll
        for (int r = 0; r < 4; ++r) cm[j][r] = 0.f;

    const unsigned* xw = reinterpret_cast<const unsigned*>(xs);
    const int arow0 = g * RW;
    const int arow1 = (g + 8) * RW;

    const int* rp = qw + (size_t)(kc * 128) * NN + nbase + 4 * g;   // chunk row 0, lane cols
    const float* sp = scales + (size_t)(kc * 8) * NN + nbase + 4 * g;

    // Prologue: weights for kt=0 and scales for grp=0
    uint4 q0 = __ldg(reinterpret_cast<const uint4*>(rp));
    uint4 q1 = __ldg(reinterpret_cast<const uint4*>(rp + NN));
    float4 sv = __ldg(reinterpret_cast<const float4*>(sp));

    for (int grp = 0; grp < 8; ++grp) {
        // Current group's fp16 scale broadcasts (exact fp32->fp16 recover)
        __half2 s2[4];
        s2[0] = __half2half2(__float2half_rn(sv.x));
        s2[1] = __half2half2(__float2half_rn(sv.y));
        s2[2] = __half2half2(__float2half_rn(sv.z));
        s2[3] = __half2half2(__float2half_rn(sv.w));
        // Prefetch next group's scales (clamped: last group re-reads itself)
        const int gnext = (grp < 7) ? grp + 1 : 7;
        float4 svn = __ldg(reinterpret_cast<const float4*>(sp + (size_t)gnext * NN));

#pragma unroll
        for (int kk8 = 0; kk8 < 8; ++kk8) {
            const int kt = grp * 8 + kk8;
            // Prefetch kt+1 weights (clamped in-bounds at chunk end)
            const int rnext = (kt < 63) ? (2 * kt + 2) : 126;
            const int* rpn = rp + (size_t)rnext * NN;
            uint4 qn0 = __ldg(reinterpret_cast<const uint4*>(rpn));
            uint4 qn1 = __ldg(reinterpret_cast<const uint4*>(rpn + NN));

            // A fragments: one LDS.64 per row (conflict-free), pa=(a0,a2)/(a1,a3)
            uint2 pa0 = *reinterpret_cast<const uint2*>(xw + arow0 + kt * 8 + 2 * t);
            uint2 pa1 = *reinterpret_cast<const uint2*>(xw + arow1 + kt * 8 + 2 * t);

            mma16816(cm[0], pa0.x, pa1.x, pa0.y, pa1.y,
                     dqs(q0.x, sh4, s2[0]), dqs(q1.x, sh4, s2[0]));
            mma16816(cm[1], pa0.x, pa1.x, pa0.y, pa1.y,
                     dqs(q0.y, sh4, s2[1]), dqs(q1.y, sh4, s2[1]));
            mma16816(cm[2], pa0.x, pa1.x, pa0.y, pa1.y,
                     dqs(q0.z, sh4, s2[2]), dqs(q1.z, sh4, s2[2]));
            mma16816(cm[3], pa0.x, pa1.x, pa0.y, pa1.y,
                     dqs(q0.w, sh4, s2[3]), dqs(q1.w, sh4, s2[3]));

            q0 = qn0;
            q1 = qn1;
        }
        sv = svn;
    }

    // ---- Store fp32 partials (tile j col c -> global col nbase+4c+j) ----
    {
        float* p = g_partial + (size_t)kc * MM * NN;
        const int col = nbase + 8 * t;
        float4 v00 = make_float4(cm[0][0], cm[1][0], cm[2][0], cm[3][0]);   // row g
        float4 v01 = make_float4(cm[0][1], cm[1][1], cm[2][1], cm[3][1]);   // row g, +4
        float4 v10 = make_float4(cm[0][2], cm[1][2], cm[2][2], cm[3][2]);   // row g+8
        float4 v11 = make_float4(cm[0][3], cm[1][3], cm[2][3], cm[3][3]);   // row g+8, +4
        *reinterpret_cast<float4*>(p + (size_t)g * NN + col)           = v00;
        *reinterpret_cast<float4*>(p + (size_t)g * NN + col + 4)       = v01;
        *reinterpret_cast<float4*>(p + (size_t)(g + 8) * NN + col)     = v10;
        *reinterpret_cast<float4*>(p + (size_t)(g + 8) * NN + col + 4) = v11;
    }
}

// One thread per 2 outputs (R7 config: measured 4.86us).
__global__ __launch_bounds__(128)
void reduce_bias_kernel(const float* __restrict__ bias, float* __restrict__ out) {
    const int i2 = blockIdx.x * 128 + threadIdx.x;
    const float2* pp = reinterpret_cast<const float2*>(g_partial);

    float2 s = pp[i2];
#pragma unroll
    for (int c = 1; c < KCH; ++c) {
        float2 b = pp[(size_t)c * (MM * NN / 2) + i2];
        s.x += b.x; s.y += b.y;
    }

    const int idx = i2 * 2;
    const int n = idx & (NN - 1);
    float2 bv = *reinterpret_cast<const float2*>(bias + n);
    // Reference fp16 epilogue: fp16(dot) + fp16(bias) in fp16.
    __half h0 = __hadd(__float2half_rn(s.x), __float2half_rn(bv.x));
    __half h1 = __hadd(__float2half_rn(s.y), __float2half_rn(bv.y));
    float2 o;
    o.x = __half2float(h0);
    o.y = __half2float(h1);
    *reinterpret_cast<float2*>(out + idx) = o;
}

extern "C" void kernel_launch(void* const* d_in, const int* in_sizes, int n_in,
                              void* d_out, int out_size) {
    // Identify inputs by element count (all distinct).
    const float* x    = nullptr;   // 131072
    const int*   qw   = nullptr;   // 8388608
    const float* sc   = nullptr;   // 524288
    const float* bias = nullptr;   // 8192
    for (int i = 0; i < n_in; ++i) {
        switch (in_sizes[i]) {
            case 131072:  x    = (const float*)d_in[i]; break;
            case 8388608: qw   = (const int*)d_in[i];   break;
            case 524288:  sc   = (const float*)d_in[i]; break;
            case 8192:    bias = (const float*)d_in[i]; break;
            default: break;
        }
    }
    float* out = (float*)d_out;

    dim3 grid(NN / 128, KCH);          // (64, 8), 128 threads (4 warps, n32 each)
    q4_gemm_mma<<<grid, 128>>>(x, qw, sc);

    reduce_bias_kernel<<<(MM * NN / 2) / 128, 128>>>(bias, out);
}

// round 14
// speedup vs baseline: 1.6008x; 1.6008x over previous
#include <cuda_runtime.h>
#include <cuda_fp16.h>
#include <cstdint>

#define MM 16
#define KK 8192
#define NN 8192
#define KCH 16            // split-K chunks
#define KC 512            // k per chunk (4 groups of 128)
#define RWW 264           // smem x row stride in WORDS (== 8 mod 32 -> LDS.64 conflict-free)

// fp32 partials: [KCH][M][N]
__device__ float g_partial[KCH * MM * NN];

__device__ __forceinline__ void mma16816(float c[4],
                                         unsigned a0, unsigned a1, unsigned a2, unsigned a3,
                                         unsigned b0, unsigned b1) {
    asm volatile(
        "mma.sync.aligned.m16n8k16.row.col.f32.f16.f16.f32 "
        "{%0,%1,%2,%3}, {%4,%5,%6,%7}, {%8,%9}, {%0,%1,%2,%3};\n"
        : "+f"(c[0]), "+f"(c[1]), "+f"(c[2]), "+f"(c[3])
        : "r"(a0), "r"(a1), "r"(a2), "r"(a3), "r"(b0), "r"(b1));
}

// Nibbles t,t+4 of w -> exact fp16x2 (q-8, q'-8), then *s in fp16 (single rounding,
// bit-identical to the reference's fp16 (q-8)*scale).
__device__ __forceinline__ unsigned dqs(unsigned w, unsigned sh4, __half2 s2) {
    unsigned v = ((w >> sh4) & 0x000F000Fu) | 0x64006400u;   // (1024+q, 1024+q')
    __half2 hv = *reinterpret_cast<__half2*>(&v);
    __half2 r = __hmul2(__hsub2(hv, __float2half2_rn(1032.0f)), s2);
    return *reinterpret_cast<unsigned*>(&r);
}

__global__ __launch_bounds__(256, 4)
void q4_gemm_mma(const float* __restrict__ x,
                 const int* __restrict__ qw,
                 const float* __restrict__ scales) {
    __shared__ __align__(16) __half xs[MM * RWW * 2];   // 16 rows * 264 words = 16896 B

    const int tid = threadIdx.x;
    const int kc = blockIdx.y;
    const int warp = tid >> 5;
    const int lane = tid & 31;
    const int g = lane >> 2;        // 0..7
    const int t = lane & 3;         // 0..3
    const unsigned sh4 = 4u * t;
    const int nbase = blockIdx.x * 256 + warp * 32;    // 8 warps, n32 each

    // ---- Stage x chunk [16][512] -> word-interleaved fp16 layout ----
    // Per k16 step kt: 8 words [b0w0,b1w0,b0w1,b1w1,b0w2,b1w2,b0w3,b1w3],
    // b0 = k 16kt..+7, b1 = +8..+15, bXwc = halves (k_c, k_{c+4}).
    for (int it = 0; it < 2; ++it) {
        int idx = it * 256 + tid;          // 512 tasks: (m, kt)
        int m = idx >> 5;
        int kt = idx & 31;
        const float* xp = x + (size_t)m * KK + kc * KC + kt * 16;
        float4 lo0 = *reinterpret_cast<const float4*>(xp);
        float4 lo1 = *reinterpret_cast<const float4*>(xp + 4);
        float4 hi0 = *reinterpret_cast<const float4*>(xp + 8);
        float4 hi1 = *reinterpret_cast<const float4*>(xp + 12);
        __half2 w0 = __floats2half2_rn(lo0.x, lo1.x);   // (k0,k4)
        __half2 w1 = __floats2half2_rn(hi0.x, hi1.x);   // (k8,k12)
        __half2 w2 = __floats2half2_rn(lo0.y, lo1.y);   // (k1,k5)
        __half2 w3 = __floats2half2_rn(hi0.y, hi1.y);   // (k9,k13)
        __half2 w4 = __floats2half2_rn(lo0.z, lo1.z);   // (k2,k6)
        __half2 w5 = __floats2half2_rn(hi0.z, hi1.z);   // (k10,k14)
        __half2 w6 = __floats2half2_rn(lo0.w, lo1.w);   // (k3,k7)
        __half2 w7 = __floats2half2_rn(hi0.w, hi1.w);   // (k11,k15)
        uint4 p0, p1;
        p0.x = *reinterpret_cast<unsigned*>(&w0);
        p0.y = *reinterpret_cast<unsigned*>(&w1);
        p0.z = *reinterpret_cast<unsigned*>(&w2);
        p0.w = *reinterpret_cast<unsigned*>(&w3);
        p1.x = *reinterpret_cast<unsigned*>(&w4);
        p1.y = *reinterpret_cast<unsigned*>(&w5);
        p1.z = *reinterpret_cast<unsigned*>(&w6);
        p1.w = *reinterpret_cast<unsigned*>(&w7);
        __half* dst = &xs[(size_t)m * RWW * 2 + kt * 16];
        *reinterpret_cast<uint4*>(dst)     = p0;
        *reinterpret_cast<uint4*>(dst + 8) = p1;
    }
    __syncthreads();

    // ---- Main loop: 4 interleaved n8-tiles (tile j col c -> n = nbase+4c+j) ----
    float cm[4][4];
#pragma unroll
    for (int j = 0; j < 4; ++j)
#pragma unroll
        for (int r = 0; r < 4; ++r) cm[j][r] = 0.f;

    const unsigned* xw = reinterpret_cast<const unsigned*>(xs);
    const int arow0 = g * RWW;
    const int arow1 = (g + 8) * RWW;

    for (int grp = 0; grp < 4; ++grp) {
        const int gidx = kc * 4 + grp;
        // fp16 scales for this lane's 4 B-columns: global cols nbase+4g..+3
        const float4 sv = __ldg(reinterpret_cast<const float4*>(
            scales + (size_t)gidx * NN + nbase + 4 * g));
        __half2 s20 = __half2half2(__float2half_rn(sv.x));
        __half2 s21 = __half2half2(__float2half_rn(sv.y));
        __half2 s22 = __half2half2(__float2half_rn(sv.z));
        __half2 s23 = __half2half2(__float2half_rn(sv.w));

#pragma unroll
        for (int kk8 = 0; kk8 < 8; ++kk8) {
            const int kt = grp * 8 + kk8;
            // Weights: lane's uint4 = rows 2kt/2kt+1 (chunk-local), cols nbase+4g..+3
            const int* rp = qw + (size_t)(kc * 64 + 2 * kt) * NN + nbase + 4 * g;
            uint4 q0 = __ldg(reinterpret_cast<const uint4*>(rp));        // row 2kt
            uint4 q1 = __ldg(reinterpret_cast<const uint4*>(rp + NN));   // row 2kt+1

            // A fragments: one LDS.64 per row (conflict-free), pa=(a0,a2)/(a1,a3)
            uint2 pa0 = *reinterpret_cast<const uint2*>(xw + arow0 + kt * 8 + 2 * t);
            uint2 pa1 = *reinterpret_cast<const uint2*>(xw + arow1 + kt * 8 + 2 * t);

            mma16816(cm[0], pa0.x, pa1.x, pa0.y, pa1.y,
                     dqs(q0.x, sh4, s20), dqs(q1.x, sh4, s20));
            mma16816(cm[1], pa0.x, pa1.x, pa0.y, pa1.y,
                     dqs(q0.y, sh4, s21), dqs(q1.y, sh4, s21));
            mma16816(cm[2], pa0.x, pa1.x, pa0.y, pa1.y,
                     dqs(q0.z, sh4, s22), dqs(q1.z, sh4, s22));
            mma16816(cm[3], pa0.x, pa1.x, pa0.y, pa1.y,
                     dqs(q0.w, sh4, s23), dqs(q1.w, sh4, s23));
        }
    }

    // ---- Store fp32 partials (tile j col c -> global col nbase+4c+j) ----
    {
        float* p = g_partial + (size_t)kc * MM * NN;
        const int col = nbase + 8 * t;
        float4 v00 = make_float4(cm[0][0], cm[1][0], cm[2][0], cm[3][0]);   // row g
        float4 v01 = make_float4(cm[0][1], cm[1][1], cm[2][1], cm[3][1]);   // row g, +4
        float4 v10 = make_float4(cm[0][2], cm[1][2], cm[2][2], cm[3][2]);   // row g+8
        float4 v11 = make_float4(cm[0][3], cm[1][3], cm[2][3], cm[3][3]);   // row g+8, +4
        *reinterpret_cast<float4*>(p + (size_t)g * NN + col)           = v00;
        *reinterpret_cast<float4*>(p + (size_t)g * NN + col + 4)       = v01;
        *reinterpret_cast<float4*>(p + (size_t)(g + 8) * NN + col)     = v10;
        *reinterpret_cast<float4*>(p + (size_t)(g + 8) * NN + col + 4) = v11;
    }
}

// One thread per 2 outputs; 16 independent partial loads each.
__global__ __launch_bounds__(256)
void reduce_bias_kernel(const float* __restrict__ bias, float* __restrict__ out) {
    const int i2 = blockIdx.x * 256 + threadIdx.x;     // 0..65535
    const float2* pp = reinterpret_cast<const float2*>(g_partial);

    float2 s = pp[i2];
#pragma unroll
    for (int c = 1; c < KCH; ++c) {
        float2 b = pp[(size_t)c * (MM * NN / 2) + i2];
        s.x += b.x; s.y += b.y;
    }

    const int idx = i2 * 2;
    const int n = idx & (NN - 1);
    float2 bv = *reinterpret_cast<const float2*>(bias + n);
    // Reference fp16 epilogue: fp16(dot) + fp16(bias) in fp16.
    __half h0 = __hadd(__float2half_rn(s.x), __float2half_rn(bv.x));
    __half h1 = __hadd(__float2half_rn(s.y), __float2half_rn(bv.y));
    float2 o;
    o.x = __half2float(h0);
    o.y = __half2float(h1);
    *reinterpret_cast<float2*>(out + idx) = o;
}

extern "C" void kernel_launch(void* const* d_in, const int* in_sizes, int n_in,
                              void* d_out, int out_size) {
    // Identify inputs by element count (all distinct).
    const float* x    = nullptr;   // 131072
    const int*   qw   = nullptr;   // 8388608
    const float* sc   = nullptr;   // 524288
    const float* bias = nullptr;   // 8192
    for (int i = 0; i < n_in; ++i) {
        switch (in_sizes[i]) {
            case 131072:  x    = (const float*)d_in[i]; break;
            case 8388608: qw   = (const int*)d_in[i];   break;
            case 524288:  sc   = (const float*)d_in[i]; break;
            case 8192:    bias = (const float*)d_in[i]; break;
            default: break;
        }
    }
    float* out = (float*)d_out;

    dim3 grid(NN / 256, KCH);          // (32, 16), 256 threads (8 warps, n32 each)
    q4_gemm_mma<<<grid, 256>>>(x, qw, sc);

    reduce_bias_kernel<<<(MM * NN / 2) / 256, 256>>>(bias, out);
}